// round 11
// baseline (speedup 1.0000x reference)
#include <cuda_runtime.h>

// heightfield: [16,1,512,512] f32 -> same shape.
// out[w] = 1 - clip( max_{r=1..16}( pad(row)[w+r] - r/10 ) - row[w], 0, 1 )
// Consolidated best-known: 256-thread CTAs (best measured occupancy),
// thread-local bias g[k]=v[k]-0.1k with 5 overlapped float4 loads,
// warp-uniform fast path (3/4 warps load unconditionally), balanced-tree
// max reductions (dependency depth 4 instead of 12), evict-first stores.

#define IM 512
#define NEG (-1e30f)
#define THREADS 256

__global__ __launch_bounds__(THREADS) void shadow_cs3(const float* __restrict__ in,
                                                      float* __restrict__ out) {
    const int gtid = blockIdx.x * THREADS + threadIdx.x;
    const int c0 = gtid << 2;              // element index (row-major)
    const int col = c0 & (IM - 1);         // column within row

    const float* p = in + c0;

    float g[20];
    // Warp spans 128 aligned columns; only wbase==384 warps can reach the pad.
    if (col < 384) {
        #pragma unroll
        for (int i = 0; i < 5; ++i) {
            float4 v = *reinterpret_cast<const float4*>(p + 4 * i);
            g[4*i+0] = v.x - 0.1f * (4*i+0);
            g[4*i+1] = v.y - 0.1f * (4*i+1);
            g[4*i+2] = v.z - 0.1f * (4*i+2);
            g[4*i+3] = v.w - 0.1f * (4*i+3);
        }
    } else {
        float4 v0 = *reinterpret_cast<const float4*>(p);
        g[0] = v0.x; g[1] = v0.y - 0.1f; g[2] = v0.z - 0.2f; g[3] = v0.w - 0.3f;
        #pragma unroll
        for (int i = 1; i < 5; ++i) {
            if (col + 4 * i <= IM - 4) {
                float4 v = *reinterpret_cast<const float4*>(p + 4 * i);
                g[4*i+0] = v.x - 0.1f * (4*i+0);
                g[4*i+1] = v.y - 0.1f * (4*i+1);
                g[4*i+2] = v.z - 0.1f * (4*i+2);
                g[4*i+3] = v.w - 0.1f * (4*i+3);
            } else {
                g[4*i+0] = NEG; g[4*i+1] = NEG; g[4*i+2] = NEG; g[4*i+3] = NEG;
            }
        }
    }

    // balanced-tree max over g[4..16] (13 values, depth 4)
    const float t45   = fmaxf(g[4],  g[5]);
    const float t67   = fmaxf(g[6],  g[7]);
    const float t89   = fmaxf(g[8],  g[9]);
    const float t1011 = fmaxf(g[10], g[11]);
    const float t1213 = fmaxf(g[12], g[13]);
    const float t1415 = fmaxf(g[14], g[15]);
    const float q0 = fmaxf(t45,  t67);
    const float q1 = fmaxf(t89,  t1011);
    const float q2 = fmaxf(t1213, t1415);
    const float cm = fmaxf(fmaxf(q0, q1), fmaxf(q2, g[16]));

    // window j: k in [j+1, j+16]; fixups paired for shallow depth
    const float a = fmaxf(g[2], g[3]);
    const float b = fmaxf(g[17], g[18]);
    const float m0 = fmaxf(cm, fmaxf(g[1], a));
    const float m1 = fmaxf(cm, fmaxf(a, g[17]));
    const float m2 = fmaxf(cm, fmaxf(g[3], b));
    const float m3 = fmaxf(cm, fmaxf(b, g[19]));

    float4 o;
    o.x = __saturatef(1.0f + (g[0] - m0));
    o.y = __saturatef(1.0f + (g[1] - m1));
    o.z = __saturatef(1.0f + (g[2] - m2));
    o.w = __saturatef(1.0f + (g[3] - m3));

    __stcs(reinterpret_cast<float4*>(out + c0), o);   // evict-first streaming store
}

extern "C" void kernel_launch(void* const* d_in, const int* in_sizes, int n_in,
                              void* d_out, int out_size) {
    const float* in = (const float*)d_in[0];
    float* out = (float*)d_out;
    const int n = in_sizes[0];                 // 4,194,304
    const int threads_total = n / 4;           // 1,048,576
    shadow_cs3<<<threads_total / THREADS, THREADS>>>(in, out);
}